// round 1
// baseline (speedup 1.0000x reference)
#include <cuda_runtime.h>
#include <math.h>

#define B_TOT 512
#define N_TOK 343
#define DIM   96
#define HEADS 3
#define HD    32
#define NW    64

// ---------------- scratch (device globals: no allocation allowed) ----------
__device__ float g_q [(size_t)B_TOT * HEADS * N_TOK * HD];   // [B][H][N][hd], pre-scaled
__device__ float g_k [(size_t)B_TOT * HEADS * N_TOK * HD];
__device__ float g_v [(size_t)B_TOT * HEADS * N_TOK * HD];
__device__ float g_ao[(size_t)B_TOT * N_TOK * DIM];          // [B][N][H*hd]

// ---------------- fast exp: FFMA-only, avoids MUFU bottleneck --------------
__device__ __forceinline__ float fast_exp(float x) {
    float y = x * 1.4426950408889634f;        // log2(e)
    y = fmaxf(y, -87.0f);                     // avoid denormal splice
    float t = y + 12582912.0f;                // round-to-nearest magic (1.5*2^23)
    float f = y - (t - 12582912.0f);          // f in [-0.5, 0.5]
    float p = 1.3333558146428443e-3f;
    p = fmaf(p, f, 9.618129107628477e-3f);
    p = fmaf(p, f, 5.550410866482158e-2f);
    p = fmaf(p, f, 2.402265069591007e-1f);
    p = fmaf(p, f, 6.931471805599453e-1f);
    p = fmaf(p, f, 1.0f);
    // splice integer part into exponent: (bits(t)<<23) == round(y)<<23
    return __int_as_float(__float_as_int(p) + (__float_as_int(t) << 23));
}

// ---------------- kernel 1: QKV GEMM + bias + scale + relayout -------------
// x[M=175616, 96] @ qkv_w^T[96, 288] + b -> split into g_q (scaled), g_k, g_v
__global__ __launch_bounds__(256, 1)
void qkv_kernel(const float* __restrict__ x,
                const float* __restrict__ w,
                const float* __restrict__ bias) {
    extern __shared__ float sm[];
    float* ws = sm;                  // [96][292]  (73 float4/row, padded)
    float* xs = sm + 96 * 292;       // [32][97]
    float* bs = xs + 32 * 97;        // [288]
    const int tid = threadIdx.x;
    const int m0  = blockIdx.x * 32;

    for (int idx = tid; idx < 288 * 96; idx += 256) {
        int c = idx / 96, k = idx - c * 96;
        ws[k * 292 + c] = w[idx];                    // transpose to k-major
    }
    for (int idx = tid; idx < 288; idx += 256) bs[idx] = bias[idx];
    for (int idx = tid; idx < 32 * 96; idx += 256) {
        int t = idx / 96, k = idx - t * 96;
        xs[t * 97 + k] = x[(size_t)(m0 + t) * 96 + k];
    }
    __syncthreads();

    const int t  = tid >> 3;     // token in tile
    const int cg = tid & 7;      // column-quad group
    float4 acc[9];
    #pragma unroll
    for (int j = 0; j < 9; j++) acc[j] = make_float4(0.f, 0.f, 0.f, 0.f);

    const float*  xrow  = xs + t * 97;
    const float4* wbase = (const float4*)ws;         // row stride 73 float4
    for (int k = 0; k < 96; k++) {
        float xv = xrow[k];
        const float4* wr = wbase + k * 73 + cg;
        #pragma unroll
        for (int j = 0; j < 9; j++) {
            float4 wv = wr[8 * j];
            acc[j].x = fmaf(xv, wv.x, acc[j].x);
            acc[j].y = fmaf(xv, wv.y, acc[j].y);
            acc[j].z = fmaf(xv, wv.z, acc[j].z);
            acc[j].w = fmaf(xv, wv.w, acc[j].w);
        }
    }

    const int m = m0 + t;
    const int b = m / N_TOK;
    const int n = m - b * N_TOK;
    #pragma unroll
    for (int j = 0; j < 9; j++) {
        int c0 = (cg + 8 * j) * 4;
        float v4[4] = {acc[j].x, acc[j].y, acc[j].z, acc[j].w};
        #pragma unroll
        for (int e = 0; e < 4; e++) {
            int c = c0 + e;
            float val = v4[e] + bs[c];
            int which = c / 96;
            int cc = c - which * 96;
            int hh = cc >> 5;
            int d  = cc & 31;
            size_t off = (((size_t)(b * HEADS + hh)) * N_TOK + n) * HD + d;
            if (which == 0)      g_q[off] = val * 0.17677669529663687f;  // /sqrt(32)
            else if (which == 1) g_k[off] = val;
            else                 g_v[off] = val;
        }
    }
}

// ---------------- kernel 2: fused attention per (b, h) ---------------------
// One CTA = one (window, head). K, V^T, probs all in smem. No block barriers
// in mainloop; softmax is warp-private (4 queries per warp per pass).
__global__ __launch_bounds__(512, 1)
void attn_kernel(const float* __restrict__ mask,
                 const float* __restrict__ rpb,
                 const int*   __restrict__ relidx) {
    extern __shared__ float sm[];
    float* ks = sm;                    // [352][33]   (rows 343..351 zeroed)
    float* vs = sm + 352 * 33;         // [32][356]   V transposed, col 343 zeroed
    float* pb = vs + 32 * 356;         // [64][344]   probs, elem 343 zeroed
    float* qs = pb + 64 * 344;         // [64][32]

    const int b    = blockIdx.x;
    const int h    = blockIdx.y;
    const int tid  = threadIdx.x;
    const int lane = tid & 31;
    const int w    = tid >> 5;         // warp 0..15

    const size_t bh_off = ((size_t)(b * HEADS + h)) * N_TOK * HD;
    const float* kg = g_k + bh_off;
    const float* vg = g_v + bh_off;
    const float* qg = g_q + bh_off;
    const float* mrow = mask + (size_t)(b & (NW - 1)) * N_TOK * N_TOK;

    for (int idx = tid; idx < N_TOK * HD; idx += 512) {
        int n = idx >> 5, d = idx & 31;
        float kvv = kg[idx];
        ks[n * 33 + d] = kvv;
        vs[d * 356 + n] = vg[idx];
    }
    for (int idx = tid; idx < 9 * 32; idx += 512) {   // zero pad rows of K
        int n = 343 + (idx >> 5), d = idx & 31;
        ks[n * 33 + d] = 0.f;
    }
    if (tid < 32) vs[tid * 356 + 343] = 0.f;
    if (tid < 64) pb[tid * 344 + 343] = 0.f;
    __syncthreads();

    for (int pass = 0; pass < 6; pass++) {
        const int ibase = pass * 64 + w * 4;

        // stage this warp's 4 query rows
        #pragma unroll
        for (int qi = 0; qi < 4; qi++) {
            int i = ibase + qi;
            qs[(w * 4 + qi) * 32 + lane] = (i < N_TOK) ? qg[i * HD + lane] : 0.f;
        }
        __syncwarp();

        // ---- scores: s[qi][tt] for j = lane + 32*tt ----
        float s[4][11];
        #pragma unroll
        for (int qi = 0; qi < 4; qi++) {
            int i = ibase + qi;
            bool iv = (i < N_TOK);
            #pragma unroll
            for (int tt = 0; tt < 11; tt++) {
                int j = lane + 32 * tt;
                float init = 0.f;
                if (iv && j < N_TOK) {
                    int rel = relidx[i * N_TOK + j];
                    init = rpb[rel * HEADS + h] + mrow[i * N_TOK + j];
                }
                s[qi][tt] = init;
            }
        }
        const float* qb = qs + w * 4 * 32;
        for (int d = 0; d < 32; d++) {
            float kv[11];
            #pragma unroll
            for (int tt = 0; tt < 11; tt++)
                kv[tt] = ks[(lane + 32 * tt) * 33 + d];
            #pragma unroll
            for (int qi = 0; qi < 4; qi++) {
                float qv = qb[qi * 32 + d];
                #pragma unroll
                for (int tt = 0; tt < 11; tt++)
                    s[qi][tt] = fmaf(qv, kv[tt], s[qi][tt]);
            }
        }

        // ---- exp + row sums (scores bounded ~|6|, max-shift unnecessary) ----
        float inv[4];
        #pragma unroll
        for (int qi = 0; qi < 4; qi++) {
            float sum = 0.f;
            float* prow = pb + (w * 4 + qi) * 344;
            #pragma unroll
            for (int tt = 0; tt < 11; tt++) {
                int j = lane + 32 * tt;
                if (j < N_TOK) {
                    float p = fast_exp(s[qi][tt]);
                    prow[j] = p;
                    sum += p;
                }
            }
            #pragma unroll
            for (int off = 16; off > 0; off >>= 1)
                sum += __shfl_xor_sync(0xffffffffu, sum, off);
            inv[qi] = 1.0f / sum;
        }
        __syncwarp();

        // ---- AV: lane owns output dim d = lane ----
        float acc0 = 0.f, acc1 = 0.f, acc2 = 0.f, acc3 = 0.f;
        const float4* vrow  = (const float4*)(vs + lane * 356);
        const float4* prow0 = (const float4*)(pb + (w * 4 + 0) * 344);
        const float4* prow1 = (const float4*)(pb + (w * 4 + 1) * 344);
        const float4* prow2 = (const float4*)(pb + (w * 4 + 2) * 344);
        const float4* prow3 = (const float4*)(pb + (w * 4 + 3) * 344);
        for (int jq = 0; jq < 86; jq++) {
            float4 vv = vrow[jq];
            float4 p0 = prow0[jq];
            acc0 = fmaf(p0.x, vv.x, acc0); acc0 = fmaf(p0.y, vv.y, acc0);
            acc0 = fmaf(p0.z, vv.z, acc0); acc0 = fmaf(p0.w, vv.w, acc0);
            float4 p1 = prow1[jq];
            acc1 = fmaf(p1.x, vv.x, acc1); acc1 = fmaf(p1.y, vv.y, acc1);
            acc1 = fmaf(p1.z, vv.z, acc1); acc1 = fmaf(p1.w, vv.w, acc1);
            float4 p2 = prow2[jq];
            acc2 = fmaf(p2.x, vv.x, acc2); acc2 = fmaf(p2.y, vv.y, acc2);
            acc2 = fmaf(p2.z, vv.z, acc2); acc2 = fmaf(p2.w, vv.w, acc2);
            float4 p3 = prow3[jq];
            acc3 = fmaf(p3.x, vv.x, acc3); acc3 = fmaf(p3.y, vv.y, acc3);
            acc3 = fmaf(p3.z, vv.z, acc3); acc3 = fmaf(p3.w, vv.w, acc3);
        }
        float accs[4] = {acc0, acc1, acc2, acc3};
        #pragma unroll
        for (int qi = 0; qi < 4; qi++) {
            int i = ibase + qi;
            if (i < N_TOK)
                g_ao[((size_t)b * N_TOK + i) * DIM + h * HD + lane] = accs[qi] * inv[qi];
        }
        __syncwarp();
    }
}

// ---------------- kernel 3: output projection ------------------------------
// g_ao[175616, 96] @ proj_w^T[96, 96] + proj_b -> out
__global__ __launch_bounds__(256, 3)
void proj_kernel(const float* __restrict__ w,
                 const float* __restrict__ bias,
                 float* __restrict__ out) {
    extern __shared__ float sm[];
    float* pw = sm;                   // [96][100]  (25 float4/row)
    float* xs = pw + 96 * 100;        // [64][97]
    float* bs = xs + 64 * 97;         // [96]
    const int tid = threadIdx.x;
    const int m0  = blockIdx.x * 64;

    for (int idx = tid; idx < 96 * 96; idx += 256) {
        int c = idx / 96, k = idx - c * 96;
        pw[k * 100 + c] = w[idx];
    }
    if (tid < 96) bs[tid] = bias[tid];
    for (int idx = tid; idx < 64 * 96; idx += 256) {
        int t = idx / 96, k = idx - t * 96;
        xs[t * 97 + k] = g_ao[(size_t)(m0 + t) * 96 + k];
    }
    __syncthreads();

    const int t  = tid >> 2;
    const int cq = tid & 3;
    float4 acc[6];
    #pragma unroll
    for (int j = 0; j < 6; j++) acc[j] = make_float4(0.f, 0.f, 0.f, 0.f);

    const float*  xrow = xs + t * 97;
    const float4* wb   = (const float4*)pw;    // row stride 25 float4
    for (int k = 0; k < 96; k++) {
        float xv = xrow[k];
        const float4* wr = wb + k * 25 + cq;
        #pragma unroll
        for (int j = 0; j < 6; j++) {
            float4 wv = wr[4 * j];
            acc[j].x = fmaf(xv, wv.x, acc[j].x);
            acc[j].y = fmaf(xv, wv.y, acc[j].y);
            acc[j].z = fmaf(xv, wv.z, acc[j].z);
            acc[j].w = fmaf(xv, wv.w, acc[j].w);
        }
    }

    #pragma unroll
    for (int j = 0; j < 6; j++) {
        int c0 = (cq + 4 * j) * 4;
        float4 r = acc[j];
        r.x += bs[c0 + 0]; r.y += bs[c0 + 1];
        r.z += bs[c0 + 2]; r.w += bs[c0 + 3];
        *(float4*)&out[(size_t)(m0 + t) * 96 + c0] = r;
    }
}

// ---------------- launch ---------------------------------------------------
extern "C" void kernel_launch(void* const* d_in, const int* in_sizes, int n_in,
                              void* d_out, int out_size) {
    const float* x      = (const float*)d_in[0];
    const float* mask   = (const float*)d_in[1];
    const float* qkv_w  = (const float*)d_in[2];
    const float* qkv_b  = (const float*)d_in[3];
    const float* proj_w = (const float*)d_in[4];
    const float* proj_b = (const float*)d_in[5];
    const float* rpb    = (const float*)d_in[6];
    const int*   relidx = (const int*)d_in[7];
    float* out = (float*)d_out;

    const int smem_qkv  = (96 * 292 + 32 * 97 + 288) * 4;            // 125,696 B
    const int smem_attn = (352 * 33 + 32 * 356 + 64 * 344 + 64 * 32) * 4;  // 188,288 B
    const int smem_proj = (96 * 100 + 64 * 97 + 96) * 4;             //  63,616 B

    cudaFuncSetAttribute(qkv_kernel,  cudaFuncAttributeMaxDynamicSharedMemorySize, smem_qkv);
    cudaFuncSetAttribute(attn_kernel, cudaFuncAttributeMaxDynamicSharedMemorySize, smem_attn);
    cudaFuncSetAttribute(proj_kernel, cudaFuncAttributeMaxDynamicSharedMemorySize, smem_proj);

    qkv_kernel <<<5488, 256, smem_qkv >>>(x, qkv_w, qkv_b);
    attn_kernel<<<dim3(512, 3), 512, smem_attn>>>(mask, rpb, relidx);
    proj_kernel<<<2744, 256, smem_proj>>>(proj_w, proj_b, out);
    (void)in_sizes; (void)n_in; (void)out_size;
}

// round 2
// speedup vs baseline: 1.4512x; 1.4512x over previous
#include <cuda_runtime.h>
#include <math.h>

#define B_TOT 512
#define N_TOK 343
#define DIM   96
#define HEADS 3
#define HD    32
#define NW    64
#define NN    (N_TOK * N_TOK)   // 117649

// ---------------- scratch (device globals: no allocation allowed) ----------
__device__ float g_q [(size_t)B_TOT * HEADS * N_TOK * HD];   // [B][H][N][hd], pre-scaled
__device__ float g_k [(size_t)B_TOT * HEADS * N_TOK * HD];
__device__ float g_v [(size_t)B_TOT * HEADS * N_TOK * HD];
__device__ float g_ao[(size_t)B_TOT * N_TOK * DIM];          // [B][N][H*hd]
__device__ float g_cb[(size_t)NW * HEADS * NN];              // combined mask+bias, 90MB

// ---------------- fast exp: FFMA-only, avoids MUFU bottleneck --------------
__device__ __forceinline__ float fast_exp(float x) {
    float y = x * 1.4426950408889634f;        // log2(e)
    y = fmaxf(y, -87.0f);
    float t = y + 12582912.0f;                // round-to-nearest magic (1.5*2^23)
    float f = y - (t - 12582912.0f);          // f in [-0.5, 0.5]
    float p = 1.3333558146428443e-3f;
    p = fmaf(p, f, 9.618129107628477e-3f);
    p = fmaf(p, f, 5.550410866482158e-2f);
    p = fmaf(p, f, 2.402265069591007e-1f);
    p = fmaf(p, f, 6.931471805599453e-1f);
    p = fmaf(p, f, 1.0f);
    return __int_as_float(__float_as_int(p) + (__float_as_int(t) << 23));
}

// ---------------- kernel 0: combined bias table ----------------------------
// g_cb[(w*3+h)][i][j] = mask[w][i][j] + rpb[relidx[i][j]][h]
__global__ __launch_bounds__(352)
void cb_kernel(const float* __restrict__ mask,
               const float* __restrict__ rpb,
               const int*   __restrict__ relidx) {
    const int i  = blockIdx.x;
    const int wh = blockIdx.y;
    const int w  = wh / HEADS;
    const int h  = wh - w * HEADS;
    const int j  = threadIdx.x;
    if (j < N_TOK) {
        int rel = relidx[i * N_TOK + j];
        g_cb[(size_t)wh * NN + i * N_TOK + j] =
            mask[(size_t)w * NN + i * N_TOK + j] + rpb[rel * HEADS + h];
    }
}

// ---------------- kernel 1: QKV GEMM third + bias + scale + relayout -------
// CTA: tile M=64 tokens x N=96 cols (one of q/k/v by blockIdx.y).
// Thread: 8 tokens x 3 cols. Per warp-k: 8 bcast + 3 LDS vs 24 FFMA.
__global__ __launch_bounds__(256, 3)
void qkv_kernel(const float* __restrict__ x,
                const float* __restrict__ w,
                const float* __restrict__ bias) {
    __shared__ float ws[96 * 100];    // [k][cc], pad 100
    __shared__ float xs[64 * 96];     // [t][k]  (broadcast reads: no pad needed)
    __shared__ float bs[96];
    const int tid   = threadIdx.x;
    const int third = blockIdx.y;
    const int m0    = blockIdx.x * 64;

    for (int idx = tid; idx < 96 * 96; idx += 256) {
        int cc = idx / 96, k = idx - cc * 96;
        ws[k * 100 + cc] = w[(third * 96 + cc) * 96 + k];
    }
    if (tid < 96) bs[tid] = bias[third * 96 + tid];
    for (int idx = tid; idx < 64 * 96; idx += 256) {
        xs[idx] = x[(size_t)m0 * 96 + idx];
    }
    __syncthreads();

    const int r = tid >> 5;    // warp: token group (8 tokens)
    const int l = tid & 31;    // lane: cols l, l+32, l+64

    float acc[8][3];
    #pragma unroll
    for (int i = 0; i < 8; i++)
        #pragma unroll
        for (int j = 0; j < 3; j++) acc[i][j] = 0.f;

    const float* xp = xs + r * 8 * 96;
    #pragma unroll 4
    for (int k = 0; k < 96; k++) {
        float wv0 = ws[k * 100 + l];
        float wv1 = ws[k * 100 + l + 32];
        float wv2 = ws[k * 100 + l + 64];
        #pragma unroll
        for (int i = 0; i < 8; i++) {
            float xv = xp[i * 96 + k];
            acc[i][0] = fmaf(xv, wv0, acc[i][0]);
            acc[i][1] = fmaf(xv, wv1, acc[i][1]);
            acc[i][2] = fmaf(xv, wv2, acc[i][2]);
        }
    }

    // epilogue: c = l + 32*j  ->  head hh=j, dim d=l (coalesced 128B stores)
    const float qscale = 0.17677669529663687f;   // 1/sqrt(32)
    #pragma unroll
    for (int i = 0; i < 8; i++) {
        int m = m0 + r * 8 + i;
        int b = m / N_TOK;
        int n = m - b * N_TOK;
        #pragma unroll
        for (int j = 0; j < 3; j++) {
            float val = acc[i][j] + bs[l + 32 * j];
            size_t off = (((size_t)(b * HEADS + j)) * N_TOK + n) * HD + l;
            if (third == 0)      g_q[off] = val * qscale;
            else if (third == 1) g_k[off] = val;
            else                 g_v[off] = val;
        }
    }
}

// ---------------- kernel 2: fused attention per (b, h) ---------------------
__global__ __launch_bounds__(512, 1)
void attn_kernel() {
    extern __shared__ float sm[];
    float* ks = sm;                    // [352][33]   (rows 343..351 zeroed)
    float* vs = sm + 352 * 33;         // [32][356]   V transposed, col 343 zeroed
    float* pb = vs + 32 * 356;         // [64][344]   probs, elem 343 zeroed
    float* qs = pb + 64 * 344;         // [64][32]

    const int b    = blockIdx.x;
    const int h    = blockIdx.y;
    const int tid  = threadIdx.x;
    const int lane = tid & 31;
    const int w    = tid >> 5;         // warp 0..15

    const size_t bh_off = ((size_t)(b * HEADS + h)) * N_TOK * HD;
    const float* kg = g_k + bh_off;
    const float* vg = g_v + bh_off;
    const float* qg = g_q + bh_off;
    const float* cbp = g_cb + (size_t)((b & (NW - 1)) * HEADS + h) * NN;

    for (int idx = tid; idx < N_TOK * HD; idx += 512) {
        int n = idx >> 5, d = idx & 31;
        ks[n * 33 + d] = kg[idx];
        vs[d * 356 + n] = vg[idx];
    }
    for (int idx = tid; idx < 9 * 32; idx += 512) {   // zero pad rows of K
        int n = 343 + (idx >> 5), d = idx & 31;
        ks[n * 33 + d] = 0.f;
    }
    if (tid < 32) vs[tid * 356 + 343] = 0.f;
    if (tid < 64) pb[tid * 344 + 343] = 0.f;
    __syncthreads();

    for (int pass = 0; pass < 6; pass++) {
        const int ibase = pass * 64 + w * 4;

        #pragma unroll
        for (int qi = 0; qi < 4; qi++) {
            int i = ibase + qi;
            qs[(w * 4 + qi) * 32 + lane] = (i < N_TOK) ? qg[i * HD + lane] : 0.f;
        }
        __syncwarp();

        // ---- scores: s[qi][tt] for j = lane + 32*tt ----
        float s[4][11];
        #pragma unroll
        for (int qi = 0; qi < 4; qi++) {
            int i = ibase + qi;
            bool iv = (i < N_TOK);
            #pragma unroll
            for (int tt = 0; tt < 11; tt++) {
                int j = lane + 32 * tt;
                float init = 0.f;
                if (iv && j < N_TOK) init = cbp[i * N_TOK + j];
                s[qi][tt] = init;
            }
        }
        const float* qb = qs + w * 4 * 32;
        for (int d = 0; d < 32; d++) {
            float kv[11];
            #pragma unroll
            for (int tt = 0; tt < 11; tt++)
                kv[tt] = ks[(lane + 32 * tt) * 33 + d];
            #pragma unroll
            for (int qi = 0; qi < 4; qi++) {
                float qv = qb[qi * 32 + d];
                #pragma unroll
                for (int tt = 0; tt < 11; tt++)
                    s[qi][tt] = fmaf(qv, kv[tt], s[qi][tt]);
            }
        }

        // ---- exp + row sums ----
        float inv[4];
        #pragma unroll
        for (int qi = 0; qi < 4; qi++) {
            float sum = 0.f;
            float* prow = pb + (w * 4 + qi) * 344;
            #pragma unroll
            for (int tt = 0; tt < 11; tt++) {
                int j = lane + 32 * tt;
                if (j < N_TOK) {
                    float p = fast_exp(s[qi][tt]);
                    prow[j] = p;
                    sum += p;
                }
            }
            #pragma unroll
            for (int off = 16; off > 0; off >>= 1)
                sum += __shfl_xor_sync(0xffffffffu, sum, off);
            inv[qi] = 1.0f / sum;
        }
        __syncwarp();

        // ---- AV: lane owns output dim d = lane ----
        float acc0 = 0.f, acc1 = 0.f, acc2 = 0.f, acc3 = 0.f;
        const float4* vrow  = (const float4*)(vs + lane * 356);
        const float4* prow0 = (const float4*)(pb + (w * 4 + 0) * 344);
        const float4* prow1 = (const float4*)(pb + (w * 4 + 1) * 344);
        const float4* prow2 = (const float4*)(pb + (w * 4 + 2) * 344);
        const float4* prow3 = (const float4*)(pb + (w * 4 + 3) * 344);
        for (int jq = 0; jq < 86; jq++) {
            float4 vv = vrow[jq];
            float4 p0 = prow0[jq];
            acc0 = fmaf(p0.x, vv.x, acc0); acc0 = fmaf(p0.y, vv.y, acc0);
            acc0 = fmaf(p0.z, vv.z, acc0); acc0 = fmaf(p0.w, vv.w, acc0);
            float4 p1 = prow1[jq];
            acc1 = fmaf(p1.x, vv.x, acc1); acc1 = fmaf(p1.y, vv.y, acc1);
            acc1 = fmaf(p1.z, vv.z, acc1); acc1 = fmaf(p1.w, vv.w, acc1);
            float4 p2 = prow2[jq];
            acc2 = fmaf(p2.x, vv.x, acc2); acc2 = fmaf(p2.y, vv.y, acc2);
            acc2 = fmaf(p2.z, vv.z, acc2); acc2 = fmaf(p2.w, vv.w, acc2);
            float4 p3 = prow3[jq];
            acc3 = fmaf(p3.x, vv.x, acc3); acc3 = fmaf(p3.y, vv.y, acc3);
            acc3 = fmaf(p3.z, vv.z, acc3); acc3 = fmaf(p3.w, vv.w, acc3);
        }
        float accs[4] = {acc0, acc1, acc2, acc3};
        #pragma unroll
        for (int qi = 0; qi < 4; qi++) {
            int i = ibase + qi;
            if (i < N_TOK)
                g_ao[((size_t)b * N_TOK + i) * DIM + h * HD + lane] = accs[qi] * inv[qi];
        }
        __syncwarp();
    }
}

// ---------------- kernel 3: output projection ------------------------------
// g_ao[175616, 96] @ proj_w^T[96, 96] + proj_b -> out. Same tiling as qkv.
__global__ __launch_bounds__(256, 3)
void proj_kernel(const float* __restrict__ w,
                 const float* __restrict__ bias,
                 float* __restrict__ out) {
    __shared__ float ws[96 * 100];
    __shared__ float xs[64 * 96];
    __shared__ float bs[96];
    const int tid = threadIdx.x;
    const int m0  = blockIdx.x * 64;

    for (int idx = tid; idx < 96 * 96; idx += 256) {
        int cc = idx / 96, k = idx - cc * 96;
        ws[k * 100 + cc] = w[cc * 96 + k];
    }
    if (tid < 96) bs[tid] = bias[tid];
    for (int idx = tid; idx < 64 * 96; idx += 256) {
        xs[idx] = g_ao[(size_t)m0 * 96 + idx];
    }
    __syncthreads();

    const int r = tid >> 5;
    const int l = tid & 31;

    float acc[8][3];
    #pragma unroll
    for (int i = 0; i < 8; i++)
        #pragma unroll
        for (int j = 0; j < 3; j++) acc[i][j] = 0.f;

    const float* xp = xs + r * 8 * 96;
    #pragma unroll 4
    for (int k = 0; k < 96; k++) {
        float wv0 = ws[k * 100 + l];
        float wv1 = ws[k * 100 + l + 32];
        float wv2 = ws[k * 100 + l + 64];
        #pragma unroll
        for (int i = 0; i < 8; i++) {
            float xv = xp[i * 96 + k];
            acc[i][0] = fmaf(xv, wv0, acc[i][0]);
            acc[i][1] = fmaf(xv, wv1, acc[i][1]);
            acc[i][2] = fmaf(xv, wv2, acc[i][2]);
        }
    }

    #pragma unroll
    for (int i = 0; i < 8; i++) {
        size_t m = m0 + r * 8 + i;
        #pragma unroll
        for (int j = 0; j < 3; j++) {
            out[m * 96 + l + 32 * j] = acc[i][j] + bs[l + 32 * j];
        }
    }
}

// ---------------- launch ---------------------------------------------------
extern "C" void kernel_launch(void* const* d_in, const int* in_sizes, int n_in,
                              void* d_out, int out_size) {
    const float* x      = (const float*)d_in[0];
    const float* mask   = (const float*)d_in[1];
    const float* qkv_w  = (const float*)d_in[2];
    const float* qkv_b  = (const float*)d_in[3];
    const float* proj_w = (const float*)d_in[4];
    const float* proj_b = (const float*)d_in[5];
    const float* rpb    = (const float*)d_in[6];
    const int*   relidx = (const int*)d_in[7];
    float* out = (float*)d_out;

    const int smem_attn = (352 * 33 + 32 * 356 + 64 * 344 + 64 * 32) * 4;  // 188,288 B
    cudaFuncSetAttribute(attn_kernel, cudaFuncAttributeMaxDynamicSharedMemorySize, smem_attn);

    cb_kernel  <<<dim3(N_TOK, NW * HEADS), 352>>>(mask, rpb, relidx);
    qkv_kernel <<<dim3(2744, 3), 256>>>(x, qkv_w, qkv_b);
    attn_kernel<<<dim3(512, 3), 512, smem_attn>>>();
    proj_kernel<<<2744, 256>>>(proj_w, proj_b, out);
    (void)in_sizes; (void)n_in; (void)out_size;
}